// round 11
// baseline (speedup 1.0000x reference)
#include <cuda_runtime.h>

// DepthLoss3D: one task per WARP (408 tasks = 51 blocks x 8 warps).
// No __syncthreads anywhere. Each warp:
//   - loads its 256-element group B (8 elems/thread, g = lane*8+r)
//   - register bitonic sort (intra-thread CE free; cross-lane = 8-wide SHFL)
//   - thread-local + warp-shuffle prefix scan
//   - diag task: sum x_(g) * (2g-255) directly from sorted regs
//   - pair task: stores run+prefix to its PRIVATE shared segment (__syncwarp),
//     then per i: 3 binary searches -> proven closed form:
//     f(x)=max(x-ds,0.2ds-x,0)-0.2ds*[x<0];
//     sum = n1*k1 - P[n1] + (T-P[n2]) - (256-n2)*k2 - 0.2ds*(256-n3)
// Epilogue: atomicAdd into memset-zeroed out[c] (proven fastest structure).

#define N_ELEM 4096

__device__ __forceinline__ int elem_index(int c, int g, int m) {
    if (c == 0)      return (g << 8) + m;
    else if (c == 1) return ((m >> 4) << 8) + (g << 4) + (m & 15);
    else             return (m << 4) + g;
}

__global__ void __launch_bounds__(256) depthloss_warp(
    const float* __restrict__ pred,   // [4096,3]
    const float* __restrict__ spac,   // [3]
    float* __restrict__ out)          // [3]
{
    __shared__ float sv[8][256];
    __shared__ float sp[8][257];

    const int lane = threadIdx.x & 31;
    const int wid  = threadIdx.x >> 5;
    const int task = blockIdx.x * 8 + wid;   // 0..407

    // Task decode: task < 48 -> diagonal (c,g); else pair (c, a>b).
    int c, a, b;
    bool diag;
    if (task < 48) {
        diag = true;
        c = task >> 4;
        a = b = task & 15;
    } else {
        diag = false;
        const int idx = task - 48;
        c = idx / 120;
        const int pq = idx - c * 120;
        a = 1;
        while ((a + 1) * a / 2 <= pq) ++a;
        b = pq - a * (a - 1) / 2;
    }

    // Load 8 group-b values per thread (global sorted-index g = lane*8+r),
    // and (pairs only) 8 p-values from group a (order irrelevant: sum over i).
    float x[8], pv[8];
#pragma unroll
    for (int r = 0; r < 8; ++r) {
        const int g = (lane << 3) | r;
        x[r] = pred[elem_index(c, b, g) * 3 + c];
    }
    if (!diag) {
#pragma unroll
        for (int r = 0; r < 8; ++r) {
            const int g = (lane << 3) | r;
            pv[r] = pred[elem_index(c, a, g) * 3 + c];
        }
    }

    // ---- Register bitonic sort of 256 elems (8/thread, ascending in g). ----
    // g = lane*8 + r. j<8: intra-thread CE. j>=8: cross-lane shfl, dist j/8.
#define CE_IN(J, K)                                                     \
    do {                                                                \
        _Pragma("unroll")                                               \
        for (int r = 0; r < 8; ++r) {                                   \
            if ((r & (J)) == 0) {                                       \
                const int g_ = (lane << 3) | r;                         \
                const bool up_ = ((g_ & (K)) == 0);                     \
                const float lo_ = x[r], hi_ = x[r | (J)];               \
                const float mn_ = fminf(lo_, hi_);                      \
                const float mx_ = fmaxf(lo_, hi_);                      \
                x[r]       = up_ ? mn_ : mx_;                           \
                x[r | (J)] = up_ ? mx_ : mn_;                           \
            }                                                           \
        }                                                               \
    } while (0)

#define CE_XL(J, K)                                                     \
    do {                                                                \
        _Pragma("unroll")                                               \
        for (int r = 0; r < 8; ++r) {                                   \
            const float o_ = __shfl_xor_sync(0xffffffffu, x[r], (J) >> 3); \
            const int g_ = (lane << 3) | r;                             \
            const bool up_ = ((g_ & (K)) == 0);                         \
            const bool mn_ = (((g_ & (J)) == 0) == up_);                \
            x[r] = mn_ ? fminf(x[r], o_) : fmaxf(x[r], o_);             \
        }                                                               \
    } while (0)

    CE_IN(1, 2);
    CE_IN(2, 4);  CE_IN(1, 4);
    CE_IN(4, 8);  CE_IN(2, 8);  CE_IN(1, 8);
    CE_XL(8, 16); CE_IN(4, 16); CE_IN(2, 16); CE_IN(1, 16);
    CE_XL(16, 32); CE_XL(8, 32); CE_IN(4, 32); CE_IN(2, 32); CE_IN(1, 32);
    CE_XL(32, 64); CE_XL(16, 64); CE_XL(8, 64);
    CE_IN(4, 64); CE_IN(2, 64); CE_IN(1, 64);
    CE_XL(64, 128); CE_XL(32, 128); CE_XL(16, 128); CE_XL(8, 128);
    CE_IN(4, 128); CE_IN(2, 128); CE_IN(1, 128);
    CE_XL(128, 512); CE_XL(64, 512); CE_XL(32, 512); CE_XL(16, 512);
    CE_XL(8, 512); CE_IN(4, 512); CE_IN(2, 512); CE_IN(1, 512);

#undef CE_IN
#undef CE_XL

    const float inv = 1.0f / ((float)N_ELEM * (float)N_ELEM);

    if (diag) {
        // sum over sorted positions g: x_(g) * (2g - 255)
        float contrib = 0.0f;
#pragma unroll
        for (int r = 0; r < 8; ++r) {
            const int g = (lane << 3) | r;
            contrib += x[r] * (float)(2 * g - 255);
        }
#pragma unroll
        for (int off = 16; off > 0; off >>= 1)
            contrib += __shfl_xor_sync(0xffffffffu, contrib, off);
        if (lane == 0) atomicAdd(&out[c], contrib * inv);
        return;
    }

    // ---- Prefix scan: thread-local then warp-exclusive over totals. ----
    float pfx[8];
    pfx[0] = x[0];
#pragma unroll
    for (int r = 1; r < 8; ++r) pfx[r] = pfx[r - 1] + x[r];
    const float tot = pfx[7];
    float run = tot;
#pragma unroll
    for (int off = 1; off < 32; off <<= 1) {
        const float y = __shfl_up_sync(0xffffffffu, run, off);
        if (lane >= off) run += y;
    }
    const float excl = run - tot;

    // ---- Publish to this warp's private segment. ----
    float* const svw = sv[wid];
    float* const spw = sp[wid];
#pragma unroll
    for (int r = 0; r < 8; ++r) {
        const int g = (lane << 3) | r;
        svw[g]     = x[r];
        spw[g + 1] = pfx[r] + excl;
    }
    if (lane == 0) spw[0] = 0.0f;
    __syncwarp();

    // ---- Closed form for 8 i's per thread. ----
    const float k  = spac[c] * 2.0f;
    const float ds = (float)a * k - (float)b * k;   // reference rounding order
    const float c1 = 0.2f * ds;
    const float T  = spw[256];

    float contrib = 0.0f;
#pragma unroll
    for (int r = 0; r < 8; ++r) {
        const float p  = pv[r];
        const float k1 = p - ds;
        const float k2 = p - c1;
        int cnt1 = 0, cnt2 = 0, cnt3 = 0;
#pragma unroll
        for (int s = 128; s > 0; s >>= 1) {
            cnt1 += (svw[cnt1 + s - 1] <  k1) ? s : 0;
            cnt2 += (svw[cnt2 + s - 1] <= k2) ? s : 0;
            cnt3 += (svw[cnt3 + s - 1] <= p ) ? s : 0;
        }
        cnt1 += (svw[cnt1] <  k1) ? 1 : 0;
        cnt2 += (svw[cnt2] <= k2) ? 1 : 0;
        cnt3 += (svw[cnt3] <= p ) ? 1 : 0;

        contrib += (float)cnt1 * k1 - spw[cnt1]
                 + (T - spw[cnt2]) - (float)(256 - cnt2) * k2
                 - c1 * (float)(256 - cnt3);
    }

#pragma unroll
    for (int off = 16; off > 0; off >>= 1)
        contrib += __shfl_xor_sync(0xffffffffu, contrib, off);
    if (lane == 0) atomicAdd(&out[c], contrib * inv);
}

extern "C" void kernel_launch(void* const* d_in, const int* in_sizes, int n_in,
                              void* d_out, int out_size)
{
    (void)in_sizes; (void)n_in; (void)out_size;
    const float* pred = (const float*)d_in[0];
    const float* spac = (const float*)d_in[1];
    float* out = (float*)d_out;

    cudaMemsetAsync(out, 0, 3 * sizeof(float));
    depthloss_warp<<<51, 256>>>(pred, spac, out);
}

// round 12
// speedup vs baseline: 1.3703x; 1.3703x over previous
#include <cuda_runtime.h>

// DepthLoss3D, single graph node. Hot path = R4 (best measured, 6.78us).
// Epilogue: per-block red.relaxed value-add + atom.release counter (no L1
// invalidate on the 407 non-final blocks); ONLY the last block pays the
// acquire (3 atomic-RMW reads), writes out[0..2], resets globals.

#define N_ELEM 4096
#define NTASKS 408   // 48 diagonal + 360 pairs

__device__ float        g_partial[3] = {0.0f, 0.0f, 0.0f};
__device__ unsigned int g_count = 0;

__device__ __forceinline__ int elem_index(int c, int g, int m) {
    if (c == 0)      return (g << 8) + m;
    else if (c == 1) return ((m >> 4) << 8) + (g << 4) + (m & 15);
    else             return (m << 4) + g;
}

__global__ void __launch_bounds__(256) depthloss_fused(
    const float* __restrict__ pred,   // [4096,3]
    const float* __restrict__ spac,   // [3]
    float* __restrict__ out)          // [3]
{
    __shared__ float sv[256];
    __shared__ float sp[257];
    __shared__ float red[8];
    __shared__ int   s_last;

    const int t    = threadIdx.x;
    const int lane = t & 31;
    const int wid  = t >> 5;
    const int bx   = blockIdx.x;

    // Task decode: bx < 48 -> diagonal (c,g); else pair (c, a>b).
    int c, a, b;
    bool diag;
    if (bx < 48) {
        diag = true;
        c = bx >> 4;
        a = b = bx & 15;
    } else {
        diag = false;
        const int idx = bx - 48;
        c = idx / 120;
        const int pq = idx - c * 120;
        a = 1;
        while ((a + 1) * a / 2 <= pq) ++a;
        b = pq - a * (a - 1) / 2;
    }

    float v = pred[elem_index(c, b, t) * 3 + c];
    float p = diag ? 0.0f : pred[elem_index(c, a, t) * 3 + c];

    // ---- Bitonic sort of v across the block (ascending by rank t). ----
    // (R4 structure: ptxas fully unrolls; in-place shared phases.)
#pragma unroll
    for (int k = 2; k <= 256; k <<= 1) {
        const bool up = ((t & k) == 0);
        int j = k >> 1;
        if (j >= 32) {
            sv[t] = v;
            __syncthreads();
            for (; j >= 32; j >>= 1) {
                if ((t & j) == 0) {
                    const float lo = sv[t], hi = sv[t | j];
                    if ((lo > hi) == up) { sv[t] = hi; sv[t | j] = lo; }
                }
                __syncthreads();
            }
            v = sv[t];
        }
#pragma unroll
        for (; j >= 1; j >>= 1) {
            const float other = __shfl_xor_sync(0xffffffffu, v, j);
            const bool keepMin = (((t & j) == 0) == up);
            v = keepMin ? fminf(v, other) : fmaxf(v, other);
        }
    }

    float partial;
    if (diag) {
        partial = v * (float)(2 * t - 255);
    } else {
        // Inclusive prefix scan of sorted v.
        float x = v;
#pragma unroll
        for (int off = 1; off < 32; off <<= 1) {
            const float y = __shfl_up_sync(0xffffffffu, x, off);
            if (lane >= off) x += y;
        }
        if (lane == 31) red[wid] = x;
        __syncthreads();
        float woff = 0.0f;
#pragma unroll
        for (int w = 0; w < 8; ++w)
            woff += (w < wid) ? red[w] : 0.0f;

        sv[t]     = v;
        sp[t + 1] = x + woff;
        if (t == 0) sp[0] = 0.0f;
        __syncthreads();

        // Closed form (proven):
        //   f(x)=max(x-ds,0.2ds-x,0)-0.2ds*[x<0]
        //   sum = n1*k1 - P[n1] + (T-P[n2]) - (256-n2)*k2 - 0.2ds*(256-n3)
        const float k  = spac[c] * 2.0f;
        const float ds = (float)a * k - (float)b * k;  // reference rounding order
        const float c1 = 0.2f * ds;
        const float k1 = p - ds;
        const float k2 = p - c1;

        int cnt1 = 0, cnt2 = 0, cnt3 = 0;
#pragma unroll
        for (int s = 128; s > 0; s >>= 1) {
            cnt1 += (sv[cnt1 + s - 1] <  k1) ? s : 0;
            cnt2 += (sv[cnt2 + s - 1] <= k2) ? s : 0;
            cnt3 += (sv[cnt3 + s - 1] <= p ) ? s : 0;
        }
        cnt1 += (sv[cnt1] <  k1) ? 1 : 0;
        cnt2 += (sv[cnt2] <= k2) ? 1 : 0;
        cnt3 += (sv[cnt3] <= p ) ? 1 : 0;

        const float T = sp[256];
        partial = (float)cnt1 * k1 - sp[cnt1]
                + (T - sp[cnt2]) - (float)(256 - cnt2) * k2
                - c1 * (float)(256 - cnt3);
    }

    // ---- Block reduction of partial. ----
#pragma unroll
    for (int off = 16; off > 0; off >>= 1)
        partial += __shfl_xor_sync(0xffffffffu, partial, off);
    __syncthreads();
    if (lane == 0) red[wid] = partial;
    __syncthreads();

    // ---- Publish: relaxed L2 value-add, then RELEASE counter (no acquire,
    //      no L1 invalidate on this path). ----
    if (t == 0) {
        const float tot = red[0] + red[1] + red[2] + red[3]
                        + red[4] + red[5] + red[6] + red[7];
        asm volatile("red.relaxed.gpu.global.add.f32 [%0], %1;"
                     :: "l"(&g_partial[c]), "f"(tot) : "memory");
        unsigned int prev;
        asm volatile("atom.release.gpu.global.add.u32 %0, [%1], 1;"
                     : "=r"(prev) : "l"(&g_count) : "memory");
        s_last = (prev == NTASKS - 1);
    }
    __syncthreads();

    // ---- Last block only: acquire-RMW reads (L2-direct), write, reset. ----
    if (s_last && t < 3) {
        float val;
        asm volatile("atom.acquire.gpu.global.add.f32 %0, [%1], %2;"
                     : "=f"(val) : "l"(&g_partial[t]), "f"(0.0f) : "memory");
        out[t] = val * (1.0f / ((float)N_ELEM * (float)N_ELEM));
        g_partial[t] = 0.0f;           // no concurrent blocks remain
        if (t == 0) g_count = 0;       // next replay ordered by launch boundary
    }
}

extern "C" void kernel_launch(void* const* d_in, const int* in_sizes, int n_in,
                              void* d_out, int out_size)
{
    (void)in_sizes; (void)n_in; (void)out_size;
    const float* pred = (const float*)d_in[0];
    const float* spac = (const float*)d_in[1];
    float* out = (float*)d_out;

    depthloss_fused<<<NTASKS, 256>>>(pred, spac, out);
}